// round 7
// baseline (speedup 1.0000x reference)
#include <cuda_runtime.h>
#include <cuda_fp16.h>
#include <math.h>

#define N_NODES 8192
#define F_IN    512
#define HID     128
#define NCLS    16
#define CAP     160
#define KSPLIT  4

#define S1_BLOCKS 512
#define S2_BLOCKS 512

// ---------------- static scratch (no allocations allowed) ----------------
__device__ float  g_dinv[N_NODES];
__device__ int    g_cnt [N_NODES];
__device__ int    g_cols[(size_t)N_NODES * CAP];
__device__ float  g_vals[(size_t)N_NODES * CAP];
__device__ uint2  g_pack[(size_t)N_NODES * CAP];          // (col, val bits)
__device__ float  g_part[(size_t)KSPLIT * N_NODES * HID]; // split-K partials
__device__ float  g_h1  [(size_t)N_NODES * HID];          // fp32 residual h
__device__ __half g_fa  [(size_t)N_NODES * HID];          // fp16 ping
__device__ __half g_fb  [(size_t)N_NODES * HID];          // fp16 pong
__device__ float  g_relu[(size_t)N_NODES * HID];          // layer-1 output fp32
__device__ float  g_h2  [(size_t)N_NODES * NCLS];         // fp32 residual h2
__device__ __half g_ca  [(size_t)N_NODES * NCLS];         // fp16 ping (layer2)
__device__ __half g_cb  [(size_t)N_NODES * NCLS];         // fp16 pong (layer2)

__device__ unsigned g_arrive[S1_BLOCKS];                  // zero-init, monotonic gens
__device__ unsigned g_release;                            // zero-init, monotonic

__device__ __constant__ float C_RES  = (float)(1.0 / 1.8);   // 1/(1+alpha)
__device__ __constant__ float C_PROP = (float)(0.8 / 1.8);   // alpha/(1+alpha)

// ---------------- acquire/release helpers (gpu scope, no SYS traffic) ----------------
__device__ __forceinline__ unsigned ld_acq(const unsigned* p) {
    unsigned v;
    asm volatile("ld.acquire.gpu.u32 %0, [%1];" : "=r"(v) : "l"(p) : "memory");
    return v;
}
__device__ __forceinline__ void st_rel(unsigned* p, unsigned v) {
    asm volatile("st.release.gpu.u32 [%0], %1;" :: "l"(p), "r"(v) : "memory");
}

// ---------------- contention-free grid barrier (requires co-resident grid) ----------
// Arrival: one release-store per block to its OWN slot (no atomic serialization).
// Block 0 scans slots in parallel, then releases one word; waiters poll with acquire.
// __threadfence() (gpu scope) emits CCTL.IVALL -> invalidates this SM's L1 so
// post-barrier cached loads of the ping-pong buffers cannot be stale.
__device__ __forceinline__ void grid_barrier(int nblocks, unsigned gen) {
    __syncthreads();
    if (blockIdx.x == 0) {
        if (threadIdx.x == 0) { __threadfence(); st_rel(&g_arrive[0], gen); }
        for (int i = threadIdx.x; i < nblocks; i += blockDim.x)
            while (ld_acq(&g_arrive[i]) < gen) { __nanosleep(20); }
        __syncthreads();
        if (threadIdx.x == 0) { st_rel(&g_release, gen); __threadfence(); }
    } else {
        if (threadIdx.x == 0) {
            __threadfence();                              // release + L1 invalidate
            st_rel(&g_arrive[blockIdx.x], gen);
            while (ld_acq(&g_release) < gen) { __nanosleep(20); }
            __threadfence();                              // acquire + L1 invalidate
        }
    }
    __syncthreads();
}

// ---------------- 1: single-pass build: ELL + dinv (one warp per row) ----------------
__global__ void build_kernel(const float* __restrict__ adj) {
    int warp = (blockIdx.x * blockDim.x + threadIdx.x) >> 5;
    int lane = threadIdx.x & 31;
    if (warp >= N_NODES) return;
    const int row = warp;
    const float4* rowp = (const float4*)(adj + (size_t)row * N_NODES);
    size_t base = (size_t)row * CAP;
    int cnt = 0;
    float s = 0.f;

    float4 v = __ldg(&rowp[lane]);
    for (int j0 = 0; j0 < N_NODES; j0 += 128) {
        float4 nv;
        if (j0 + 128 < N_NODES) nv = __ldg(&rowp[(j0 + 128) / 4 + lane]);
        int j = j0 + lane * 4;
        v.x += (j + 0 == row) ? 1.f : 0.f;
        v.y += (j + 1 == row) ? 1.f : 0.f;
        v.z += (j + 2 == row) ? 1.f : 0.f;
        v.w += (j + 3 == row) ? 1.f : 0.f;
        s += v.x + v.y + v.z + v.w;
        int c = (v.x != 0.f) + (v.y != 0.f) + (v.z != 0.f) + (v.w != 0.f);
        int incl = c;
#pragma unroll
        for (int d = 1; d < 32; d <<= 1) {
            int t = __shfl_up_sync(0xffffffffu, incl, d);
            if (lane >= d) incl += t;
        }
        int total = __shfl_sync(0xffffffffu, incl, 31);
        int w = cnt + incl - c;
        float vv[4] = {v.x, v.y, v.z, v.w};
#pragma unroll
        for (int q = 0; q < 4; q++) {
            if (vv[q] != 0.f) {
                if (w < CAP) { g_cols[base + w] = j + q; g_vals[base + w] = vv[q]; }
                w++;
            }
        }
        cnt += total;
        v = nv;
    }
#pragma unroll
    for (int d = 16; d; d >>= 1) s += __shfl_xor_sync(0xffffffffu, s, d);
    if (lane == 0) {
        g_cnt[row]  = (cnt < CAP) ? cnt : CAP;
        g_dinv[row] = rsqrtf(fmaxf(s, 1e-12f));
    }
}

// ---------------- 2: split-K SGEMM  part[z] = A[:, zK:(z+1)K] @ B[zK:(z+1)K, :] ------
__global__ void gemm1_kernel(const float* __restrict__ A, const float* __restrict__ B) {
    const int BM = 64, BN = 64, BK = 16, KC = F_IN / KSPLIT;  // 128
    __shared__ float As[BK][BM];
    __shared__ float Bs[BK][BN];
    int m0 = blockIdx.x * BM;
    int n0 = blockIdx.y * BN;
    int kz = blockIdx.z;
    float* P = g_part + (size_t)kz * N_NODES * HID;
    int t  = threadIdx.x;
    int tx = t & 15, ty = t >> 4;
    float acc[4][4] = {};
    for (int k0 = kz * KC; k0 < kz * KC + KC; k0 += BK) {
        {
            int r = t >> 2, c4 = t & 3;
            float4 a = *(const float4*)(A + (size_t)(m0 + r) * F_IN + k0 + c4 * 4);
            As[c4 * 4 + 0][r] = a.x; As[c4 * 4 + 1][r] = a.y;
            As[c4 * 4 + 2][r] = a.z; As[c4 * 4 + 3][r] = a.w;
        }
        {
            int kr = t >> 4, c4 = t & 15;
            float4 b = *(const float4*)(B + (size_t)(k0 + kr) * HID + n0 + c4 * 4);
            Bs[kr][c4 * 4 + 0] = b.x; Bs[kr][c4 * 4 + 1] = b.y;
            Bs[kr][c4 * 4 + 2] = b.z; Bs[kr][c4 * 4 + 3] = b.w;
        }
        __syncthreads();
#pragma unroll
        for (int k = 0; k < BK; k++) {
            float av[4], bv[4];
#pragma unroll
            for (int i = 0; i < 4; i++) av[i] = As[k][ty * 4 + i];
#pragma unroll
            for (int j = 0; j < 4; j++) bv[j] = Bs[k][tx * 4 + j];
#pragma unroll
            for (int i = 0; i < 4; i++)
#pragma unroll
                for (int j = 0; j < 4; j++)
                    acc[i][j] = fmaf(av[i], bv[j], acc[i][j]);
        }
        __syncthreads();
    }
#pragma unroll
    for (int i = 0; i < 4; i++) {
        size_t off = (size_t)(m0 + ty * 4 + i) * HID + n0 + tx * 4;
        *(float4*)(P + off) = make_float4(acc[i][0], acc[i][1], acc[i][2], acc[i][3]);
    }
}

// ---------------- 3: S1 persistent: scale/pack + reduce + 8 diffusion steps + relu ----
__global__ void __launch_bounds__(256, 4) s1_kernel(const float* __restrict__ bias) {
    const int tid  = blockIdx.x * 256 + threadIdx.x;     // 0 .. 131071
    const int gw   = tid >> 5;                           // global warp 0..4095
    const int lane = tid & 31;
    unsigned bgen = ld_acq(&g_release);                  // stable pre-kernel value

    // --- preamble A: reduce split-K partials -> g_h1 fp32 + g_fa fp16 ---
    {
        const size_t TOT = (size_t)N_NODES * HID / 4;    // 262144 float4
        const float4* p0 = (const float4*)g_part;
        for (size_t i = tid; i < TOT; i += (size_t)S1_BLOCKS * 256) {
            float4 a = p0[i];
            float4 b = p0[TOT + i];
            float4 c = p0[2 * TOT + i];
            float4 d = p0[3 * TOT + i];
            float4 r;
            r.x = (a.x + b.x) + (c.x + d.x);
            r.y = (a.y + b.y) + (c.y + d.y);
            r.z = (a.z + b.z) + (c.z + d.z);
            r.w = (a.w + b.w) + (c.w + d.w);
            ((float4*)g_h1)[i] = r;
            __half2 h0 = __floats2half2_rn(r.x, r.y);
            __half2 h1 = __floats2half2_rn(r.z, r.w);
            ((uint2*)g_fa)[i] = make_uint2(*(unsigned*)&h0, *(unsigned*)&h1);
        }
    }
    // --- preamble B: scale vals and pack (col,val) ---
    for (int row = gw; row < N_NODES; row += 4096) {
        size_t base = (size_t)row * CAP;
        int cnt = g_cnt[row];
        float di = g_dinv[row];
        for (int e = lane; e < cnt; e += 32) {
            int c = g_cols[base + e];
            float v = g_vals[base + e] * di * __ldg(&g_dinv[c]);
            g_pack[base + e] = make_uint2((unsigned)c, __float_as_uint(v));
        }
    }
    grid_barrier(S1_BLOCKS, ++bgen);

    // --- 8 diffusion steps, fp16 gather / fp32 accum; last step fuses bias+relu ---
    __half* const bufs[2] = {g_fa, g_fb};
    for (int step = 0; step < 8; step++) {
        const bool fin = (step == 7);
        const uint2* __restrict__ inv = (const uint2*)bufs[step & 1];
        __half*      outh             = bufs[(step + 1) & 1];
        for (int row = gw; row < N_NODES; row += 4096) {     // exactly 2 rows/warp
            size_t base = (size_t)row * CAP;
            int cnt = g_cnt[row];
            const uint2* __restrict__ ev = g_pack + base;
            float ax = 0.f, ay = 0.f, az = 0.f, aw = 0.f;
#pragma unroll 4
            for (int e = 0; e < cnt; e++) {
                uint2 p = __ldg(&ev[e]);
                int   c = (int)p.x;
                float v = __uint_as_float(p.y);
                uint2 o = __ldg(&inv[(size_t)c * 32 + lane]);
                float2 f0 = __half22float2(*(__half2*)&o.x);
                float2 f1 = __half22float2(*(__half2*)&o.y);
                ax = fmaf(v, f0.x, ax);
                ay = fmaf(v, f0.y, ay);
                az = fmaf(v, f1.x, az);
                aw = fmaf(v, f1.y, aw);
            }
            float4 hh = ((const float4*)g_h1)[(size_t)row * 32 + lane];
            float4 r;
            r.x = C_PROP * ax + C_RES * hh.x;
            r.y = C_PROP * ay + C_RES * hh.y;
            r.z = C_PROP * az + C_RES * hh.z;
            r.w = C_PROP * aw + C_RES * hh.w;
            if (fin) {
                float4 b = ((const float4*)bias)[lane];
                r.x = fmaxf(r.x + b.x, 0.f);
                r.y = fmaxf(r.y + b.y, 0.f);
                r.z = fmaxf(r.z + b.z, 0.f);
                r.w = fmaxf(r.w + b.w, 0.f);
                ((float4*)g_relu)[(size_t)row * 32 + lane] = r;
            } else {
                __half2 h0 = __floats2half2_rn(r.x, r.y);
                __half2 h1 = __floats2half2_rn(r.z, r.w);
                ((uint2*)outh)[(size_t)row * 32 + lane] =
                    make_uint2(*(unsigned*)&h0, *(unsigned*)&h1);
            }
        }
        if (!fin) grid_barrier(S1_BLOCKS, ++bgen);
    }
}

// ---------------- 4: S2 persistent: gemm2 + 8 diffusion steps + log_softmax ----------
// 512 blocks x 256 thr; 16 rows/block; 16 threads/row = two 8-lane edge-halves.
__global__ void __launch_bounds__(256, 4) s2_kernel(const float* __restrict__ W2,
                                                    const float* __restrict__ bias,
                                                    float* __restrict__ outp) {
    __shared__ float sW[HID * NCLS];                      // 8 KB
    const int t    = threadIdx.x;
    const int rib  = t >> 4;                              // row-in-block 0..15
    const int l16  = t & 15;                              // class index 0..15
    const int l8   = l16 & 7;                             // half2 lane
    const int eg   = l16 >> 3;                            // edge group 0/1
    const int row  = blockIdx.x * 16 + rib;
    unsigned bgen = ld_acq(&g_release);

    // --- preamble: h2 = relu_out @ W2 (one class per thread) ---
    for (int i = t; i < HID * NCLS; i += 256) sW[i] = W2[i];
    __syncthreads();
    {
        const float* Hr = g_relu + (size_t)row * HID;
        float a = 0.f;
#pragma unroll 8
        for (int k = 0; k < HID; k++)
            a = fmaf(__ldg(&Hr[k]), sW[k * NCLS + l16], a);
        size_t off = (size_t)row * NCLS + l16;
        g_h2[off] = a;
        g_ca[off] = __float2half_rn(a);
    }
    grid_barrier(S2_BLOCKS, ++bgen);

    // --- 8 diffusion steps, fp16 gather, edges split across two 8-lane groups ---
    __half* const bufs[2] = {g_ca, g_cb};
    const size_t base = (size_t)row * CAP;
    const int cnt = g_cnt[row];
    for (int step = 0; step < 8; step++) {
        const bool fin = (step == 7);
        const unsigned* __restrict__ inv = (const unsigned*)bufs[step & 1];
        __half*         outh             = bufs[(step + 1) & 1];
        const uint2* __restrict__ ev = g_pack + base;
        float a0 = 0.f, a1 = 0.f;
        for (int e = eg; e < cnt; e += 2) {
            uint2 p = __ldg(&ev[e]);
            int   c = (int)p.x;
            float v = __uint_as_float(p.y);
            unsigned o = __ldg(&inv[(size_t)c * 8 + l8]);
            float2 f = __half22float2(*(__half2*)&o);
            a0 = fmaf(v, f.x, a0);
            a1 = fmaf(v, f.y, a1);
        }
        // combine the two edge-halves (both halves end with the full sum)
        a0 += __shfl_xor_sync(0xffffffffu, a0, 8, 16);
        a1 += __shfl_xor_sync(0xffffffffu, a1, 8, 16);
        float2 hh = ((const float2*)g_h2)[(size_t)row * 8 + l8];
        float r0 = C_PROP * a0 + C_RES * hh.x;
        float r1 = C_PROP * a1 + C_RES * hh.y;
        if (fin) {
            float2 b = ((const float2*)bias)[l8];
            r0 += b.x;
            r1 += b.y;
            float m = fmaxf(r0, r1);
#pragma unroll
            for (int s = 1; s < 8; s <<= 1)
                m = fmaxf(m, __shfl_xor_sync(0xffffffffu, m, s, 8));
            float ssum = expf(r0 - m) + expf(r1 - m);
#pragma unroll
            for (int s = 1; s < 8; s <<= 1)
                ssum += __shfl_xor_sync(0xffffffffu, ssum, s, 8);
            float lse = m + logf(ssum);
            if (eg == 0)
                ((float2*)outp)[(size_t)row * 8 + l8] = make_float2(r0 - lse, r1 - lse);
        } else {
            if (eg == 0) {
                __half2 hv = __floats2half2_rn(r0, r1);
                ((unsigned*)outh)[(size_t)row * 8 + l8] = *(unsigned*)&hv;
            }
            grid_barrier(S2_BLOCKS, ++bgen);
        }
    }
}

// ---------------- launch: 4 kernels total ----------------
extern "C" void kernel_launch(void* const* d_in, const int* in_sizes, int n_in,
                              void* d_out, int out_size) {
    const float* x   = (const float*)d_in[0];
    const float* adj = (const float*)d_in[1];
    const float* W1  = (const float*)d_in[2];
    const float* b1  = (const float*)d_in[3];
    const float* W2  = (const float*)d_in[4];
    const float* b2  = (const float*)d_in[5];
    float* out = (float*)d_out;

    build_kernel<<<N_NODES / 8, 256>>>(adj);
    gemm1_kernel<<<dim3(N_NODES / 64, HID / 64, KSPLIT), 256>>>(x, W1);
    s1_kernel<<<S1_BLOCKS, 256>>>(b1);
    s2_kernel<<<S2_BLOCKS, 256>>>(W2, b2, out);
}

// round 8
// speedup vs baseline: 1.5296x; 1.5296x over previous
#include <cuda_runtime.h>
#include <cuda_fp16.h>
#include <math.h>

#define N_NODES 8192
#define F_IN    512
#define HID     128
#define NCLS    16
#define CAP     160
#define KSPLIT  4

// ---------------- static scratch (no allocations allowed) ----------------
__device__ float  g_dinv[N_NODES];
__device__ int    g_cnt [N_NODES];
__device__ int    g_cols[(size_t)N_NODES * CAP];
__device__ float  g_vals[(size_t)N_NODES * CAP];
__device__ uint2  g_pack[(size_t)N_NODES * CAP];          // (col, val bits)
__device__ float  g_part[(size_t)KSPLIT * N_NODES * HID]; // split-K partials
__device__ float  g_h1  [(size_t)N_NODES * HID];          // fp32 residual h
__device__ __half g_fa  [(size_t)N_NODES * HID];          // fp16 ping
__device__ __half g_fb  [(size_t)N_NODES * HID];          // fp16 pong
__device__ float  g_relu[(size_t)N_NODES * HID];          // layer-1 output fp32
__device__ float  g_h2  [(size_t)N_NODES * NCLS];         // fp32 residual h2
__device__ __half g_ca  [(size_t)N_NODES * NCLS];         // fp16 ping (layer2)
__device__ __half g_cb  [(size_t)N_NODES * NCLS];         // fp16 pong (layer2)

__device__ __constant__ float C_RES  = (float)(1.0 / 1.8);   // 1/(1+alpha)
__device__ __constant__ float C_PROP = (float)(0.8 / 1.8);   // alpha/(1+alpha)

// ---------------- 1: single-pass build: ELL + dinv (one warp per row) ----------------
__global__ void build_kernel(const float* __restrict__ adj) {
    int warp = (blockIdx.x * blockDim.x + threadIdx.x) >> 5;
    int lane = threadIdx.x & 31;
    if (warp >= N_NODES) return;
    const int row = warp;
    const float4* rowp = (const float4*)(adj + (size_t)row * N_NODES);
    size_t base = (size_t)row * CAP;
    int cnt = 0;
    float s = 0.f;

    float4 v = __ldg(&rowp[lane]);
    for (int j0 = 0; j0 < N_NODES; j0 += 128) {
        float4 nv;
        if (j0 + 128 < N_NODES) nv = __ldg(&rowp[(j0 + 128) / 4 + lane]);
        int j = j0 + lane * 4;
        v.x += (j + 0 == row) ? 1.f : 0.f;
        v.y += (j + 1 == row) ? 1.f : 0.f;
        v.z += (j + 2 == row) ? 1.f : 0.f;
        v.w += (j + 3 == row) ? 1.f : 0.f;
        s += v.x + v.y + v.z + v.w;
        int c = (v.x != 0.f) + (v.y != 0.f) + (v.z != 0.f) + (v.w != 0.f);
        int incl = c;
#pragma unroll
        for (int d = 1; d < 32; d <<= 1) {
            int t = __shfl_up_sync(0xffffffffu, incl, d);
            if (lane >= d) incl += t;
        }
        int total = __shfl_sync(0xffffffffu, incl, 31);
        int w = cnt + incl - c;
        float vv[4] = {v.x, v.y, v.z, v.w};
#pragma unroll
        for (int q = 0; q < 4; q++) {
            if (vv[q] != 0.f) {
                if (w < CAP) { g_cols[base + w] = j + q; g_vals[base + w] = vv[q]; }
                w++;
            }
        }
        cnt += total;
        v = nv;
    }
#pragma unroll
    for (int d = 16; d; d >>= 1) s += __shfl_xor_sync(0xffffffffu, s, d);
    if (lane == 0) {
        g_cnt[row]  = (cnt < CAP) ? cnt : CAP;
        g_dinv[row] = rsqrtf(fmaxf(s, 1e-12f));      // dinv fused (degree is row-local)
    }
}

// ---------------- 2: scale vals and pack (col,val) ----------------
__global__ void scale_kernel() {
    int warp = (blockIdx.x * blockDim.x + threadIdx.x) >> 5;
    int lane = threadIdx.x & 31;
    if (warp >= N_NODES) return;
    size_t base = (size_t)warp * CAP;
    int cnt = g_cnt[warp];
    float di = g_dinv[warp];
    for (int e = lane; e < cnt; e += 32) {
        int c = g_cols[base + e];
        float v = g_vals[base + e] * di * __ldg(&g_dinv[c]);
        g_pack[base + e] = make_uint2((unsigned)c, __float_as_uint(v));
    }
}

// ---------------- 3: split-K SGEMM, 8x4 thread tile (BM=128, BN=64, BK=16) ----------
// part[z] = A[:, z*128:(z+1)*128] @ B[z*128:(z+1)*128, :]
__global__ void __launch_bounds__(256) gemm1_kernel(const float* __restrict__ A,
                                                    const float* __restrict__ B) {
    const int BM = 128, BN = 64, BK = 16, KC = F_IN / KSPLIT;  // KC = 128
    __shared__ float As[BK][BM];     // 8 KB, stored transposed
    __shared__ float Bs[BK][BN];     // 4 KB
    const int m0 = blockIdx.x * BM;
    const int n0 = blockIdx.y * BN;
    const int kz = blockIdx.z;
    float* P = g_part + (size_t)kz * N_NODES * HID;
    const int t  = threadIdx.x;
    const int tx = t & 15;           // 0..15 -> 4 cols each
    const int ty = t >> 4;           // 0..15 -> 8 rows each
    const int ar = t >> 1;           // A-load row 0..127
    const int ac = (t & 1) * 8;      // A-load col group (8 cols = 2 float4)
    const int bk = t >> 4;           // B-load k-row 0..15
    const int bc = (t & 15) * 4;     // B-load col (float4)

    float acc[8][4] = {};
    for (int k0 = kz * KC; k0 < kz * KC + KC; k0 += BK) {
        {   // A tile -> transposed smem
            const float* ap = A + (size_t)(m0 + ar) * F_IN + k0 + ac;
            float4 a0 = *(const float4*)(ap);
            float4 a1 = *(const float4*)(ap + 4);
            As[ac + 0][ar] = a0.x; As[ac + 1][ar] = a0.y;
            As[ac + 2][ar] = a0.z; As[ac + 3][ar] = a0.w;
            As[ac + 4][ar] = a1.x; As[ac + 5][ar] = a1.y;
            As[ac + 6][ar] = a1.z; As[ac + 7][ar] = a1.w;
        }
        {   // B tile
            float4 b = *(const float4*)(B + (size_t)(k0 + bk) * HID + n0 + bc);
            Bs[bk][bc + 0] = b.x; Bs[bk][bc + 1] = b.y;
            Bs[bk][bc + 2] = b.z; Bs[bk][bc + 3] = b.w;
        }
        __syncthreads();
#pragma unroll
        for (int k = 0; k < BK; k++) {
            float av[8], bv[4];
#pragma unroll
            for (int i = 0; i < 8; i++) av[i] = As[k][ty * 8 + i];
#pragma unroll
            for (int j = 0; j < 4; j++) bv[j] = Bs[k][tx * 4 + j];
#pragma unroll
            for (int i = 0; i < 8; i++)
#pragma unroll
                for (int j = 0; j < 4; j++)
                    acc[i][j] = fmaf(av[i], bv[j], acc[i][j]);
        }
        __syncthreads();
    }
#pragma unroll
    for (int i = 0; i < 8; i++) {
        size_t off = (size_t)(m0 + ty * 8 + i) * HID + n0 + tx * 4;
        *(float4*)(P + off) = make_float4(acc[i][0], acc[i][1], acc[i][2], acc[i][3]);
    }
}

// ---------------- 3b: reduce split-K partials -> fp32 h1 + fp16 fa ----------------
__global__ void reduce_kernel() {
    size_t i = (size_t)(blockIdx.x * blockDim.x + threadIdx.x);   // float4 index
    const size_t TOT = (size_t)N_NODES * HID / 4;
    if (i >= TOT) return;
    const float4* p0 = (const float4*)g_part;
    float4 a = p0[i];
    float4 b = p0[TOT + i];
    float4 c = p0[2 * TOT + i];
    float4 d = p0[3 * TOT + i];
    float4 r;
    r.x = (a.x + b.x) + (c.x + d.x);
    r.y = (a.y + b.y) + (c.y + d.y);
    r.z = (a.z + b.z) + (c.z + d.z);
    r.w = (a.w + b.w) + (c.w + d.w);
    ((float4*)g_h1)[i] = r;
    __half2 h0 = __floats2half2_rn(r.x, r.y);
    __half2 h1 = __floats2half2_rn(r.z, r.w);
    ((uint2*)g_fa)[i] = make_uint2(*(unsigned*)&h0, *(unsigned*)&h1);
}

// ---------------- 4: SpMM diffusion step, F=128, fp16 gather / fp32 accum --------------
template <bool FINAL>
__global__ void spmm_h16(const __half* __restrict__ in, const float* __restrict__ h,
                         __half* __restrict__ out, float* __restrict__ outf,
                         const float* __restrict__ bias) {
    int warp = threadIdx.x >> 5;
    int lane = threadIdx.x & 31;
    int row  = blockIdx.x * 8 + warp;
    size_t base = (size_t)row * CAP;
    int cnt = g_cnt[row];
    const uint2* __restrict__ ev  = g_pack + base;
    const uint2* __restrict__ inv = (const uint2*)in;
    float ax = 0.f, ay = 0.f, az = 0.f, aw = 0.f;
#pragma unroll 4
    for (int e = 0; e < cnt; e++) {
        uint2 p = __ldg(&ev[e]);
        int   c = (int)p.x;
        float v = __uint_as_float(p.y);
        uint2 o = __ldg(&inv[(size_t)c * 32 + lane]);
        float2 f0 = __half22float2(*(__half2*)&o.x);
        float2 f1 = __half22float2(*(__half2*)&o.y);
        ax = fmaf(v, f0.x, ax);
        ay = fmaf(v, f0.y, ay);
        az = fmaf(v, f1.x, az);
        aw = fmaf(v, f1.y, aw);
    }
    float4 hh = ((const float4*)h)[(size_t)row * 32 + lane];
    float4 r;
    r.x = C_PROP * ax + C_RES * hh.x;
    r.y = C_PROP * ay + C_RES * hh.y;
    r.z = C_PROP * az + C_RES * hh.z;
    r.w = C_PROP * aw + C_RES * hh.w;
    if (FINAL) {
        float4 b = ((const float4*)bias)[lane];
        r.x = fmaxf(r.x + b.x, 0.f);
        r.y = fmaxf(r.y + b.y, 0.f);
        r.z = fmaxf(r.z + b.z, 0.f);
        r.w = fmaxf(r.w + b.w, 0.f);
        ((float4*)outf)[(size_t)row * 32 + lane] = r;
    } else {
        __half2 h0 = __floats2half2_rn(r.x, r.y);
        __half2 h1 = __floats2half2_rn(r.z, r.w);
        ((uint2*)out)[(size_t)row * 32 + lane] = make_uint2(*(unsigned*)&h0, *(unsigned*)&h1);
    }
}

// ---------------- 5: small GEMM  h2 = H @ W2 (fp32 residual + fp16 copy) --------------
__global__ void gemm2_kernel(const float* __restrict__ Hm, const float* __restrict__ W2) {
    __shared__ float sW[128 * 16];
    __shared__ float sH[16 * 128];
    int t = threadIdx.x;
    int row0 = blockIdx.x * 16;
    for (int i = t; i < 128 * 16; i += 256) sW[i] = W2[i];
    for (int i = t; i < 16 * 128; i += 256) {
        int r = i >> 7, k = i & 127;
        sH[i] = Hm[(size_t)(row0 + r) * 128 + k];
    }
    __syncthreads();
    int r = t >> 4, c = t & 15;
    float acc = 0.f;
#pragma unroll 8
    for (int k = 0; k < 128; k++) acc = fmaf(sH[r * 128 + k], sW[k * 16 + c], acc);
    size_t off = (size_t)(row0 + r) * 16 + c;
    g_h2[off] = acc;
    g_ca[off] = __float2half_rn(acc);
}

// ---------------- 6: SpMM diffusion step, F=16 fp16 gather (8 lanes/row, half2) -------
template <bool FINAL>
__global__ void spmm_c16(const __half* __restrict__ in, const float* __restrict__ h,
                         __half* __restrict__ out, float* __restrict__ outf,
                         const float* __restrict__ bias) {
    int sub  = threadIdx.x >> 3;          // row within block (32 rows/block)
    int lane = threadIdx.x & 7;           // 8 lanes per row, half2 each
    int row  = blockIdx.x * 32 + sub;
    size_t base = (size_t)row * CAP;
    int cnt = g_cnt[row];
    const uint2* __restrict__ ev = g_pack + base;
    const unsigned* __restrict__ inv = (const unsigned*)in;   // half2 per lane
    float a0 = 0.f, a1 = 0.f;
#pragma unroll 4
    for (int e = 0; e < cnt; e++) {
        uint2 p = __ldg(&ev[e]);
        int   c = (int)p.x;
        float v = __uint_as_float(p.y);
        unsigned o = __ldg(&inv[(size_t)c * 8 + lane]);
        float2 f = __half22float2(*(__half2*)&o);
        a0 = fmaf(v, f.x, a0);
        a1 = fmaf(v, f.y, a1);
    }
    float2 hh = ((const float2*)h)[(size_t)row * 8 + lane];
    float r0 = C_PROP * a0 + C_RES * hh.x;
    float r1 = C_PROP * a1 + C_RES * hh.y;
    if (FINAL) {
        float2 b = ((const float2*)bias)[lane];
        r0 += b.x;
        r1 += b.y;
        float m = fmaxf(r0, r1);
#pragma unroll
        for (int s = 1; s < 8; s <<= 1)
            m = fmaxf(m, __shfl_xor_sync(0xffffffffu, m, s, 8));
        float ssum = expf(r0 - m) + expf(r1 - m);
#pragma unroll
        for (int s = 1; s < 8; s <<= 1)
            ssum += __shfl_xor_sync(0xffffffffu, ssum, s, 8);
        float lse = m + logf(ssum);
        r0 -= lse;
        r1 -= lse;
        ((float2*)outf)[(size_t)row * 8 + lane] = make_float2(r0, r1);
    } else {
        __half2 hv = __floats2half2_rn(r0, r1);
        ((unsigned*)out)[(size_t)row * 8 + lane] = *(unsigned*)&hv;
    }
}

// ---------------- launch ----------------
extern "C" void kernel_launch(void* const* d_in, const int* in_sizes, int n_in,
                              void* d_out, int out_size) {
    const float* x   = (const float*)d_in[0];
    const float* adj = (const float*)d_in[1];
    const float* W1  = (const float*)d_in[2];
    const float* b1  = (const float*)d_in[3];
    const float* W2  = (const float*)d_in[4];
    const float* b2  = (const float*)d_in[5];
    float* out = (float*)d_out;

    void *ph1, *pfa, *pfb, *prl, *ph2, *pca, *pcb;
    cudaGetSymbolAddress(&ph1, g_h1);
    cudaGetSymbolAddress(&pfa, g_fa);
    cudaGetSymbolAddress(&pfb, g_fb);
    cudaGetSymbolAddress(&prl, g_relu);
    cudaGetSymbolAddress(&ph2, g_h2);
    cudaGetSymbolAddress(&pca, g_ca);
    cudaGetSymbolAddress(&pcb, g_cb);
    float*  h1 = (float*)ph1;
    __half* fa = (__half*)pfa;
    __half* fb = (__half*)pfb;
    float*  rl = (float*)prl;
    float*  h2 = (float*)ph2;
    __half* ca = (__half*)pca;
    __half* cb = (__half*)pcb;

    // build normalized sparse adjacency (single pass over adj; dinv fused)
    build_kernel<<<N_NODES / 8, 256>>>(adj);
    scale_kernel<<<N_NODES / 8, 256>>>();

    // layer 1: h = x @ W1 via split-K (8x4 tile); 8 diffusion steps (fp16 gather)
    gemm1_kernel<<<dim3(N_NODES / 128, HID / 64, KSPLIT), 256>>>(x, W1);
    reduce_kernel<<<N_NODES * HID / 4 / 256, 256>>>();
    spmm_h16<false><<<N_NODES / 8, 256>>>(fa, h1, fb, nullptr, b1);
    spmm_h16<false><<<N_NODES / 8, 256>>>(fb, h1, fa, nullptr, b1);
    spmm_h16<false><<<N_NODES / 8, 256>>>(fa, h1, fb, nullptr, b1);
    spmm_h16<false><<<N_NODES / 8, 256>>>(fb, h1, fa, nullptr, b1);
    spmm_h16<false><<<N_NODES / 8, 256>>>(fa, h1, fb, nullptr, b1);
    spmm_h16<false><<<N_NODES / 8, 256>>>(fb, h1, fa, nullptr, b1);
    spmm_h16<false><<<N_NODES / 8, 256>>>(fa, h1, fb, nullptr, b1);
    spmm_h16<true ><<<N_NODES / 8, 256>>>(fb, h1, nullptr, rl, b1);  // relu(out+b1) fp32

    // layer 2: h2 = relu_out @ W2; 8 fp16 diffusion steps; final = bias + log_softmax
    gemm2_kernel<<<N_NODES / 16, 256>>>(rl, W2);
    spmm_c16<false><<<N_NODES / 32, 256>>>(ca, h2, cb, nullptr, b2);
    spmm_c16<false><<<N_NODES / 32, 256>>>(cb, h2, ca, nullptr, b2);
    spmm_c16<false><<<N_NODES / 32, 256>>>(ca, h2, cb, nullptr, b2);
    spmm_c16<false><<<N_NODES / 32, 256>>>(cb, h2, ca, nullptr, b2);
    spmm_c16<false><<<N_NODES / 32, 256>>>(ca, h2, cb, nullptr, b2);
    spmm_c16<false><<<N_NODES / 32, 256>>>(cb, h2, ca, nullptr, b2);
    spmm_c16<false><<<N_NODES / 32, 256>>>(ca, h2, cb, nullptr, b2);
    spmm_c16<true ><<<N_NODES / 32, 256>>>(cb, h2, nullptr, out, b2);
}

// round 9
// speedup vs baseline: 1.5373x; 1.0050x over previous
#include <cuda_runtime.h>
#include <cuda_fp16.h>
#include <math.h>

#define N_NODES 8192
#define F_IN    512
#define HID     128
#define NCLS    16
#define CAP     160
#define KSPLIT  4

// ---------------- static scratch (no allocations allowed) ----------------
__device__ float  g_dinv[N_NODES];
__device__ int    g_cnt [N_NODES];
__device__ int    g_cols[(size_t)N_NODES * CAP];
__device__ float  g_vals[(size_t)N_NODES * CAP];
__device__ uint2  g_pack[(size_t)N_NODES * CAP];          // (col, val bits)
__device__ float  g_part[(size_t)KSPLIT * N_NODES * HID]; // split-K partials
__device__ float  g_h1  [(size_t)N_NODES * HID];          // fp32 residual h
__device__ __half g_fa  [(size_t)N_NODES * HID];          // fp16 ping
__device__ __half g_fb  [(size_t)N_NODES * HID];          // fp16 pong
__device__ float  g_relu[(size_t)N_NODES * HID];          // layer-1 output fp32
__device__ float  g_h2  [(size_t)N_NODES * NCLS];         // fp32 residual h2
__device__ __half g_ca  [(size_t)N_NODES * NCLS];         // fp16 ping (layer2)
__device__ __half g_cb  [(size_t)N_NODES * NCLS];         // fp16 pong (layer2)

__device__ __constant__ float C_RES  = (float)(1.0 / 1.8);   // 1/(1+alpha)
__device__ __constant__ float C_PROP = (float)(0.8 / 1.8);   // alpha/(1+alpha)

// ---------------- 1: single-pass build: ELL + dinv (one warp per row) ----------------
__global__ void build_kernel(const float* __restrict__ adj) {
    int warp = (blockIdx.x * blockDim.x + threadIdx.x) >> 5;
    int lane = threadIdx.x & 31;
    if (warp >= N_NODES) return;
    const int row = warp;
    const float4* rowp = (const float4*)(adj + (size_t)row * N_NODES);
    size_t base = (size_t)row * CAP;
    int cnt = 0;
    float s = 0.f;

    float4 v = __ldg(&rowp[lane]);
    for (int j0 = 0; j0 < N_NODES; j0 += 128) {
        float4 nv;
        if (j0 + 128 < N_NODES) nv = __ldg(&rowp[(j0 + 128) / 4 + lane]);
        int j = j0 + lane * 4;
        v.x += (j + 0 == row) ? 1.f : 0.f;
        v.y += (j + 1 == row) ? 1.f : 0.f;
        v.z += (j + 2 == row) ? 1.f : 0.f;
        v.w += (j + 3 == row) ? 1.f : 0.f;
        s += v.x + v.y + v.z + v.w;
        int c = (v.x != 0.f) + (v.y != 0.f) + (v.z != 0.f) + (v.w != 0.f);
        int incl = c;
#pragma unroll
        for (int d = 1; d < 32; d <<= 1) {
            int t = __shfl_up_sync(0xffffffffu, incl, d);
            if (lane >= d) incl += t;
        }
        int total = __shfl_sync(0xffffffffu, incl, 31);
        int w = cnt + incl - c;
        float vv[4] = {v.x, v.y, v.z, v.w};
#pragma unroll
        for (int q = 0; q < 4; q++) {
            if (vv[q] != 0.f) {
                if (w < CAP) { g_cols[base + w] = j + q; g_vals[base + w] = vv[q]; }
                w++;
            }
        }
        cnt += total;
        v = nv;
    }
#pragma unroll
    for (int d = 16; d; d >>= 1) s += __shfl_xor_sync(0xffffffffu, s, d);
    if (lane == 0) {
        g_cnt[row]  = (cnt < CAP) ? cnt : CAP;
        g_dinv[row] = rsqrtf(fmaxf(s, 1e-12f));
    }
}

// ---------------- 2: scale vals and pack (col,val) ----------------
__global__ void scale_kernel() {
    int warp = (blockIdx.x * blockDim.x + threadIdx.x) >> 5;
    int lane = threadIdx.x & 31;
    if (warp >= N_NODES) return;
    size_t base = (size_t)warp * CAP;
    int cnt = g_cnt[warp];
    float di = g_dinv[warp];
    for (int e = lane; e < cnt; e += 32) {
        int c = g_cols[base + e];
        float v = g_vals[base + e] * di * __ldg(&g_dinv[c]);
        g_pack[base + e] = make_uint2((unsigned)c, __float_as_uint(v));
    }
}

// ---------------- 3: split-K SGEMM, 8x4 thread tile (BM=128, BN=64, BK=16) ----------
__global__ void __launch_bounds__(256) gemm1_kernel(const float* __restrict__ A,
                                                    const float* __restrict__ B) {
    const int BM = 128, BN = 64, BK = 16, KC = F_IN / KSPLIT;  // KC = 128
    __shared__ float As[BK][BM];
    __shared__ float Bs[BK][BN];
    const int m0 = blockIdx.x * BM;
    const int n0 = blockIdx.y * BN;
    const int kz = blockIdx.z;
    float* P = g_part + (size_t)kz * N_NODES * HID;
    const int t  = threadIdx.x;
    const int tx = t & 15;
    const int ty = t >> 4;
    const int ar = t >> 1;
    const int ac = (t & 1) * 8;
    const int bk = t >> 4;
    const int bc = (t & 15) * 4;

    float acc[8][4] = {};
    for (int k0 = kz * KC; k0 < kz * KC + KC; k0 += BK) {
        {
            const float* ap = A + (size_t)(m0 + ar) * F_IN + k0 + ac;
            float4 a0 = *(const float4*)(ap);
            float4 a1 = *(const float4*)(ap + 4);
            As[ac + 0][ar] = a0.x; As[ac + 1][ar] = a0.y;
            As[ac + 2][ar] = a0.z; As[ac + 3][ar] = a0.w;
            As[ac + 4][ar] = a1.x; As[ac + 5][ar] = a1.y;
            As[ac + 6][ar] = a1.z; As[ac + 7][ar] = a1.w;
        }
        {
            float4 b = *(const float4*)(B + (size_t)(k0 + bk) * HID + n0 + bc);
            Bs[bk][bc + 0] = b.x; Bs[bk][bc + 1] = b.y;
            Bs[bk][bc + 2] = b.z; Bs[bk][bc + 3] = b.w;
        }
        __syncthreads();
#pragma unroll
        for (int k = 0; k < BK; k++) {
            float av[8], bv[4];
#pragma unroll
            for (int i = 0; i < 8; i++) av[i] = As[k][ty * 8 + i];
#pragma unroll
            for (int j = 0; j < 4; j++) bv[j] = Bs[k][tx * 4 + j];
#pragma unroll
            for (int i = 0; i < 8; i++)
#pragma unroll
                for (int j = 0; j < 4; j++)
                    acc[i][j] = fmaf(av[i], bv[j], acc[i][j]);
        }
        __syncthreads();
    }
#pragma unroll
    for (int i = 0; i < 8; i++) {
        size_t off = (size_t)(m0 + ty * 8 + i) * HID + n0 + tx * 4;
        *(float4*)(P + off) = make_float4(acc[i][0], acc[i][1], acc[i][2], acc[i][3]);
    }
}

// ---------------- 3b: reduce split-K partials (2 groups/thread for MLP=8) ------------
__global__ void reduce_kernel() {
    const size_t TOT = (size_t)N_NODES * HID / 4;        // 262144 float4
    size_t i0 = (size_t)blockIdx.x * 512 + threadIdx.x;  // group A
    size_t i1 = i0 + 256;                                // group B (independent)
    const float4* p0 = (const float4*)g_part;
#pragma unroll
    for (int g = 0; g < 2; g++) {
        size_t i = g ? i1 : i0;
        if (i >= TOT) continue;
        float4 a = p0[i];
        float4 b = p0[TOT + i];
        float4 c = p0[2 * TOT + i];
        float4 d = p0[3 * TOT + i];
        float4 r;
        r.x = (a.x + b.x) + (c.x + d.x);
        r.y = (a.y + b.y) + (c.y + d.y);
        r.z = (a.z + b.z) + (c.z + d.z);
        r.w = (a.w + b.w) + (c.w + d.w);
        ((float4*)g_h1)[i] = r;
        __half2 h0 = __floats2half2_rn(r.x, r.y);
        __half2 h1 = __floats2half2_rn(r.z, r.w);
        ((uint2*)g_fa)[i] = make_uint2(*(unsigned*)&h0, *(unsigned*)&h1);
    }
}

// ---------------- 4: SpMM diffusion step, F=128, fp16 gather / fp32 accum --------------
template <bool FINAL>
__global__ void spmm_h16(const __half* __restrict__ in, const float* __restrict__ h,
                         __half* __restrict__ out, float* __restrict__ outf,
                         const float* __restrict__ bias) {
    int warp = threadIdx.x >> 5;
    int lane = threadIdx.x & 31;
    int row  = blockIdx.x * 8 + warp;
    size_t base = (size_t)row * CAP;
    int cnt = g_cnt[row];
    const uint2* __restrict__ ev  = g_pack + base;
    const uint2* __restrict__ inv = (const uint2*)in;
    float ax = 0.f, ay = 0.f, az = 0.f, aw = 0.f;
#pragma unroll 8
    for (int e = 0; e < cnt; e++) {
        uint2 p = __ldg(&ev[e]);
        int   c = (int)p.x;
        float v = __uint_as_float(p.y);
        uint2 o = __ldg(&inv[(size_t)c * 32 + lane]);
        float2 f0 = __half22float2(*(__half2*)&o.x);
        float2 f1 = __half22float2(*(__half2*)&o.y);
        ax = fmaf(v, f0.x, ax);
        ay = fmaf(v, f0.y, ay);
        az = fmaf(v, f1.x, az);
        aw = fmaf(v, f1.y, aw);
    }
    float4 hh = ((const float4*)h)[(size_t)row * 32 + lane];
    float4 r;
    r.x = C_PROP * ax + C_RES * hh.x;
    r.y = C_PROP * ay + C_RES * hh.y;
    r.z = C_PROP * az + C_RES * hh.z;
    r.w = C_PROP * aw + C_RES * hh.w;
    if (FINAL) {
        float4 b = ((const float4*)bias)[lane];
        r.x = fmaxf(r.x + b.x, 0.f);
        r.y = fmaxf(r.y + b.y, 0.f);
        r.z = fmaxf(r.z + b.z, 0.f);
        r.w = fmaxf(r.w + b.w, 0.f);
        ((float4*)outf)[(size_t)row * 32 + lane] = r;
    } else {
        __half2 h0 = __floats2half2_rn(r.x, r.y);
        __half2 h1 = __floats2half2_rn(r.z, r.w);
        ((uint2*)out)[(size_t)row * 32 + lane] = make_uint2(*(unsigned*)&h0, *(unsigned*)&h1);
    }
}

// ---------------- 5: small GEMM  h2 = H @ W2 (fp32 residual + fp16 copy) --------------
__global__ void gemm2_kernel(const float* __restrict__ Hm, const float* __restrict__ W2) {
    __shared__ float sW[128 * 16];
    __shared__ float sH[16 * 128];
    int t = threadIdx.x;
    int row0 = blockIdx.x * 16;
    for (int i = t; i < 128 * 16; i += 256) sW[i] = W2[i];
    for (int i = t; i < 16 * 128; i += 256) {
        int r = i >> 7, k = i & 127;
        sH[i] = Hm[(size_t)(row0 + r) * 128 + k];
    }
    __syncthreads();
    int r = t >> 4, c = t & 15;
    float acc = 0.f;
#pragma unroll 8
    for (int k = 0; k < 128; k++) acc = fmaf(sH[r * 128 + k], sW[k * 16 + c], acc);
    size_t off = (size_t)(row0 + r) * 16 + c;
    g_h2[off] = acc;
    g_ca[off] = __float2half_rn(acc);
}

// ---------------- 6: SpMM diffusion step, F=16 fp16 gather (8 lanes/row, half2) -------
template <bool FINAL>
__global__ void spmm_c16(const __half* __restrict__ in, const float* __restrict__ h,
                         __half* __restrict__ out, float* __restrict__ outf,
                         const float* __restrict__ bias) {
    int sub  = threadIdx.x >> 3;
    int lane = threadIdx.x & 7;
    int row  = blockIdx.x * 32 + sub;
    size_t base = (size_t)row * CAP;
    int cnt = g_cnt[row];
    const uint2* __restrict__ ev = g_pack + base;
    const unsigned* __restrict__ inv = (const unsigned*)in;
    float a0 = 0.f, a1 = 0.f;
#pragma unroll 8
    for (int e = 0; e < cnt; e++) {
        uint2 p = __ldg(&ev[e]);
        int   c = (int)p.x;
        float v = __uint_as_float(p.y);
        unsigned o = __ldg(&inv[(size_t)c * 8 + lane]);
        float2 f = __half22float2(*(__half2*)&o);
        a0 = fmaf(v, f.x, a0);
        a1 = fmaf(v, f.y, a1);
    }
    float2 hh = ((const float2*)h)[(size_t)row * 8 + lane];
    float r0 = C_PROP * a0 + C_RES * hh.x;
    float r1 = C_PROP * a1 + C_RES * hh.y;
    if (FINAL) {
        float2 b = ((const float2*)bias)[lane];
        r0 += b.x;
        r1 += b.y;
        float m = fmaxf(r0, r1);
#pragma unroll
        for (int s = 1; s < 8; s <<= 1)
            m = fmaxf(m, __shfl_xor_sync(0xffffffffu, m, s, 8));
        float ssum = expf(r0 - m) + expf(r1 - m);
#pragma unroll
        for (int s = 1; s < 8; s <<= 1)
            ssum += __shfl_xor_sync(0xffffffffu, ssum, s, 8);
        float lse = m + logf(ssum);
        r0 -= lse;
        r1 -= lse;
        ((float2*)outf)[(size_t)row * 8 + lane] = make_float2(r0, r1);
    } else {
        __half2 hv = __floats2half2_rn(r0, r1);
        ((unsigned*)out)[(size_t)row * 8 + lane] = *(unsigned*)&hv;
    }
}

// ---------------- launch: build||gemm1 stream-forked ----------------
extern "C" void kernel_launch(void* const* d_in, const int* in_sizes, int n_in,
                              void* d_out, int out_size) {
    const float* x   = (const float*)d_in[0];
    const float* adj = (const float*)d_in[1];
    const float* W1  = (const float*)d_in[2];
    const float* b1  = (const float*)d_in[3];
    const float* W2  = (const float*)d_in[4];
    const float* b2  = (const float*)d_in[5];
    float* out = (float*)d_out;

    void *ph1, *pfa, *pfb, *prl, *ph2, *pca, *pcb;
    cudaGetSymbolAddress(&ph1, g_h1);
    cudaGetSymbolAddress(&pfa, g_fa);
    cudaGetSymbolAddress(&pfb, g_fb);
    cudaGetSymbolAddress(&prl, g_relu);
    cudaGetSymbolAddress(&ph2, g_h2);
    cudaGetSymbolAddress(&pca, g_ca);
    cudaGetSymbolAddress(&pcb, g_cb);
    float*  h1 = (float*)ph1;
    __half* fa = (__half*)pfa;
    __half* fb = (__half*)pfb;
    float*  rl = (float*)prl;
    float*  h2 = (float*)ph2;
    __half* ca = (__half*)pca;
    __half* cb = (__half*)pcb;

    // fork a side stream for the independent gemm1->reduce chain
    cudaStream_t sB;
    cudaStreamCreateWithFlags(&sB, cudaStreamNonBlocking);
    cudaEvent_t eFork, eJoin;
    cudaEventCreateWithFlags(&eFork, cudaEventDisableTiming);
    cudaEventCreateWithFlags(&eJoin, cudaEventDisableTiming);

    cudaEventRecord(eFork, 0);
    cudaStreamWaitEvent(sB, eFork, 0);

    // branch B: layer-1 dense transform (compute-bound)
    gemm1_kernel<<<dim3(N_NODES / 128, HID / 64, KSPLIT), 256, 0, sB>>>(x, W1);
    reduce_kernel<<<N_NODES * HID / 4 / 512, 256, 0, sB>>>();
    cudaEventRecord(eJoin, sB);

    // branch A (main stream): adjacency build (DRAM-bound)
    build_kernel<<<N_NODES / 8, 256>>>(adj);
    scale_kernel<<<N_NODES / 8, 256>>>();

    cudaStreamWaitEvent(0, eJoin, 0);   // join: spmm needs pack + fa + h1

    // layer 1: 8 diffusion steps (fp16 gather)
    spmm_h16<false><<<N_NODES / 8, 256>>>(fa, h1, fb, nullptr, b1);
    spmm_h16<false><<<N_NODES / 8, 256>>>(fb, h1, fa, nullptr, b1);
    spmm_h16<false><<<N_NODES / 8, 256>>>(fa, h1, fb, nullptr, b1);
    spmm_h16<false><<<N_NODES / 8, 256>>>(fb, h1, fa, nullptr, b1);
    spmm_h16<false><<<N_NODES / 8, 256>>>(fa, h1, fb, nullptr, b1);
    spmm_h16<false><<<N_NODES / 8, 256>>>(fb, h1, fa, nullptr, b1);
    spmm_h16<false><<<N_NODES / 8, 256>>>(fa, h1, fb, nullptr, b1);
    spmm_h16<true ><<<N_NODES / 8, 256>>>(fb, h1, nullptr, rl, b1);  // relu(out+b1) fp32

    // layer 2: h2 = relu_out @ W2; 8 fp16 diffusion steps; final = bias + log_softmax
    gemm2_kernel<<<N_NODES / 16, 256>>>(rl, W2);
    spmm_c16<false><<<N_NODES / 32, 256>>>(ca, h2, cb, nullptr, b2);
    spmm_c16<false><<<N_NODES / 32, 256>>>(cb, h2, ca, nullptr, b2);
    spmm_c16<false><<<N_NODES / 32, 256>>>(ca, h2, cb, nullptr, b2);
    spmm_c16<false><<<N_NODES / 32, 256>>>(cb, h2, ca, nullptr, b2);
    spmm_c16<false><<<N_NODES / 32, 256>>>(ca, h2, cb, nullptr, b2);
    spmm_c16<false><<<N_NODES / 32, 256>>>(cb, h2, ca, nullptr, b2);
    spmm_c16<false><<<N_NODES / 32, 256>>>(ca, h2, cb, nullptr, b2);
    spmm_c16<true ><<<N_NODES / 32, 256>>>(cb, h2, nullptr, out, b2);

    cudaEventDestroy(eFork);
    cudaEventDestroy(eJoin);
    cudaStreamDestroy(sB);
}

// round 10
// speedup vs baseline: 1.7318x; 1.1265x over previous
#include <cuda_runtime.h>
#include <cuda_fp16.h>
#include <math.h>

#define N_NODES 8192
#define F_IN    512
#define HID     128
#define NCLS    16
#define CAP     160
#define KSPLIT  4

// ---------------- static scratch (no allocations allowed) ----------------
__device__ float  g_dinv[N_NODES];
__device__ int    g_cnt [N_NODES];
__device__ int    g_cols[(size_t)N_NODES * CAP];
__device__ float  g_vals[(size_t)N_NODES * CAP];
__device__ uint2  g_pack[(size_t)N_NODES * CAP];          // (col, val bits)
__device__ float  g_part[(size_t)KSPLIT * N_NODES * HID]; // split-K partials
__device__ float  g_h1  [(size_t)N_NODES * HID];          // fp32 residual h
__device__ __half g_fa  [(size_t)N_NODES * HID];          // fp16 ping
__device__ __half g_fb  [(size_t)N_NODES * HID];          // fp16 pong
__device__ float  g_relu[(size_t)N_NODES * HID];          // layer-1 output fp32
__device__ float  g_h2  [(size_t)N_NODES * NCLS];         // fp32 residual h2
__device__ __half g_ca  [(size_t)N_NODES * NCLS];         // fp16 ping (layer2)
__device__ __half g_cb  [(size_t)N_NODES * NCLS];         // fp16 pong (layer2)

__device__ __constant__ float C_RES  = (float)(1.0 / 1.8);   // 1/(1+alpha)
__device__ __constant__ float C_PROP = (float)(0.8 / 1.8);   // alpha/(1+alpha)

// ---------------- 1: single-pass build: ELL + dinv (one warp per row) ----------------
__global__ void build_kernel(const float* __restrict__ adj) {
    int warp = (blockIdx.x * blockDim.x + threadIdx.x) >> 5;
    int lane = threadIdx.x & 31;
    if (warp >= N_NODES) return;
    const int row = warp;
    const float4* rowp = (const float4*)(adj + (size_t)row * N_NODES);
    size_t base = (size_t)row * CAP;
    int cnt = 0;
    float s = 0.f;

    float4 v = __ldg(&rowp[lane]);
    for (int j0 = 0; j0 < N_NODES; j0 += 128) {
        float4 nv;
        if (j0 + 128 < N_NODES) nv = __ldg(&rowp[(j0 + 128) / 4 + lane]);
        int j = j0 + lane * 4;
        v.x += (j + 0 == row) ? 1.f : 0.f;
        v.y += (j + 1 == row) ? 1.f : 0.f;
        v.z += (j + 2 == row) ? 1.f : 0.f;
        v.w += (j + 3 == row) ? 1.f : 0.f;
        s += v.x + v.y + v.z + v.w;
        int c = (v.x != 0.f) + (v.y != 0.f) + (v.z != 0.f) + (v.w != 0.f);
        int incl = c;
#pragma unroll
        for (int d = 1; d < 32; d <<= 1) {
            int t = __shfl_up_sync(0xffffffffu, incl, d);
            if (lane >= d) incl += t;
        }
        int total = __shfl_sync(0xffffffffu, incl, 31);
        int w = cnt + incl - c;
        float vv[4] = {v.x, v.y, v.z, v.w};
#pragma unroll
        for (int q = 0; q < 4; q++) {
            if (vv[q] != 0.f) {
                if (w < CAP) { g_cols[base + w] = j + q; g_vals[base + w] = vv[q]; }
                w++;
            }
        }
        cnt += total;
        v = nv;
    }
#pragma unroll
    for (int d = 16; d; d >>= 1) s += __shfl_xor_sync(0xffffffffu, s, d);
    if (lane == 0) {
        g_cnt[row]  = (cnt < CAP) ? cnt : CAP;
        g_dinv[row] = rsqrtf(fmaxf(s, 1e-12f));
    }
}

// ---------------- 2: split-K SGEMM, 8x4 thread tile (BM=128, BN=64, BK=16) ----------
__global__ void __launch_bounds__(256) gemm1_kernel(const float* __restrict__ A,
                                                    const float* __restrict__ B) {
    const int BM = 128, BN = 64, BK = 16, KC = F_IN / KSPLIT;  // KC = 128
    __shared__ float As[BK][BM];
    __shared__ float Bs[BK][BN];
    const int m0 = blockIdx.x * BM;
    const int n0 = blockIdx.y * BN;
    const int kz = blockIdx.z;
    float* P = g_part + (size_t)kz * N_NODES * HID;
    const int t  = threadIdx.x;
    const int tx = t & 15;
    const int ty = t >> 4;
    const int ar = t >> 1;
    const int ac = (t & 1) * 8;
    const int bk = t >> 4;
    const int bc = (t & 15) * 4;

    float acc[8][4] = {};
    for (int k0 = kz * KC; k0 < kz * KC + KC; k0 += BK) {
        {
            const float* ap = A + (size_t)(m0 + ar) * F_IN + k0 + ac;
            float4 a0 = *(const float4*)(ap);
            float4 a1 = *(const float4*)(ap + 4);
            As[ac + 0][ar] = a0.x; As[ac + 1][ar] = a0.y;
            As[ac + 2][ar] = a0.z; As[ac + 3][ar] = a0.w;
            As[ac + 4][ar] = a1.x; As[ac + 5][ar] = a1.y;
            As[ac + 6][ar] = a1.z; As[ac + 7][ar] = a1.w;
        }
        {
            float4 b = *(const float4*)(B + (size_t)(k0 + bk) * HID + n0 + bc);
            Bs[bk][bc + 0] = b.x; Bs[bk][bc + 1] = b.y;
            Bs[bk][bc + 2] = b.z; Bs[bk][bc + 3] = b.w;
        }
        __syncthreads();
#pragma unroll
        for (int k = 0; k < BK; k++) {
            float av[8], bv[4];
#pragma unroll
            for (int i = 0; i < 8; i++) av[i] = As[k][ty * 8 + i];
#pragma unroll
            for (int j = 0; j < 4; j++) bv[j] = Bs[k][tx * 4 + j];
#pragma unroll
            for (int i = 0; i < 8; i++)
#pragma unroll
                for (int j = 0; j < 4; j++)
                    acc[i][j] = fmaf(av[i], bv[j], acc[i][j]);
        }
        __syncthreads();
    }
#pragma unroll
    for (int i = 0; i < 8; i++) {
        size_t off = (size_t)(m0 + ty * 8 + i) * HID + n0 + tx * 4;
        *(float4*)(P + off) = make_float4(acc[i][0], acc[i][1], acc[i][2], acc[i][3]);
    }
}

// ---------------- 2b: reduce split-K partials (2 groups/thread for MLP=8) ------------
__global__ void reduce_kernel() {
    const size_t TOT = (size_t)N_NODES * HID / 4;        // 262144 float4
    size_t i0 = (size_t)blockIdx.x * 512 + threadIdx.x;
    size_t i1 = i0 + 256;
    const float4* p0 = (const float4*)g_part;
#pragma unroll
    for (int g = 0; g < 2; g++) {
        size_t i = g ? i1 : i0;
        if (i >= TOT) continue;
        float4 a = p0[i];
        float4 b = p0[TOT + i];
        float4 c = p0[2 * TOT + i];
        float4 d = p0[3 * TOT + i];
        float4 r;
        r.x = (a.x + b.x) + (c.x + d.x);
        r.y = (a.y + b.y) + (c.y + d.y);
        r.z = (a.z + b.z) + (c.z + d.z);
        r.w = (a.w + b.w) + (c.w + d.w);
        ((float4*)g_h1)[i] = r;
        __half2 h0 = __floats2half2_rn(r.x, r.y);
        __half2 h1 = __floats2half2_rn(r.z, r.w);
        ((uint2*)g_fa)[i] = make_uint2(*(unsigned*)&h0, *(unsigned*)&h1);
    }
}

// ---------------- 3: SpMM diffusion step, F=128, 2 warps/row, fp16 gather ------------
// SCALE: first step also computes normalized edge weights and writes g_pack.
template <bool SCALE, bool FINAL>
__global__ void spmm_h16(const __half* __restrict__ in, const float* __restrict__ h,
                         __half* __restrict__ out, float* __restrict__ outf,
                         const float* __restrict__ bias) {
    __shared__ float4 partial[4][32];
    const int warp = threadIdx.x >> 5;                  // 0..7
    const int lane = threadIdx.x & 31;
    const int rib  = warp >> 1;                         // row-in-block 0..3
    const int half = warp & 1;                          // edge half 0/1
    const int row  = blockIdx.x * 4 + rib;
    const size_t base = (size_t)row * CAP;
    const int cnt = g_cnt[row];
    const uint2* __restrict__ inv = (const uint2*)in;
    float ax = 0.f, ay = 0.f, az = 0.f, aw = 0.f;

    if (SCALE) {
        const float di = g_dinv[row];
        for (int e = half; e < cnt; e += 2) {
            int   c = __ldg(&g_cols[base + e]);
            float v = __ldg(&g_vals[base + e]) * di * __ldg(&g_dinv[c]);
            if (lane == 0) g_pack[base + e] = make_uint2((unsigned)c, __float_as_uint(v));
            uint2 o = __ldg(&inv[(size_t)c * 32 + lane]);
            float2 f0 = __half22float2(*(__half2*)&o.x);
            float2 f1 = __half22float2(*(__half2*)&o.y);
            ax = fmaf(v, f0.x, ax);
            ay = fmaf(v, f0.y, ay);
            az = fmaf(v, f1.x, az);
            aw = fmaf(v, f1.y, aw);
        }
    } else {
        const uint2* __restrict__ ev = g_pack + base;
#pragma unroll 4
        for (int e = half; e < cnt; e += 2) {
            uint2 p = __ldg(&ev[e]);
            int   c = (int)p.x;
            float v = __uint_as_float(p.y);
            uint2 o = __ldg(&inv[(size_t)c * 32 + lane]);
            float2 f0 = __half22float2(*(__half2*)&o.x);
            float2 f1 = __half22float2(*(__half2*)&o.y);
            ax = fmaf(v, f0.x, ax);
            ay = fmaf(v, f0.y, ay);
            az = fmaf(v, f1.x, az);
            aw = fmaf(v, f1.y, aw);
        }
    }

    if (half == 0) partial[rib][lane] = make_float4(ax, ay, az, aw);
    __syncthreads();
    if (half == 1) {
        float4 p = partial[rib][lane];
        ax += p.x; ay += p.y; az += p.z; aw += p.w;
        float4 hh = ((const float4*)h)[(size_t)row * 32 + lane];
        float4 r;
        r.x = C_PROP * ax + C_RES * hh.x;
        r.y = C_PROP * ay + C_RES * hh.y;
        r.z = C_PROP * az + C_RES * hh.z;
        r.w = C_PROP * aw + C_RES * hh.w;
        if (FINAL) {
            float4 b = ((const float4*)bias)[lane];
            r.x = fmaxf(r.x + b.x, 0.f);
            r.y = fmaxf(r.y + b.y, 0.f);
            r.z = fmaxf(r.z + b.z, 0.f);
            r.w = fmaxf(r.w + b.w, 0.f);
            ((float4*)outf)[(size_t)row * 32 + lane] = r;
        } else {
            __half2 h0 = __floats2half2_rn(r.x, r.y);
            __half2 h1 = __floats2half2_rn(r.z, r.w);
            ((uint2*)out)[(size_t)row * 32 + lane] =
                make_uint2(*(unsigned*)&h0, *(unsigned*)&h1);
        }
    }
}

// ---------------- 4: small GEMM  h2 = H @ W2 (fp32 residual + fp16 copy) --------------
__global__ void gemm2_kernel(const float* __restrict__ Hm, const float* __restrict__ W2) {
    __shared__ float sW[128 * 16];
    __shared__ float sH[16 * 128];
    int t = threadIdx.x;
    int row0 = blockIdx.x * 16;
    for (int i = t; i < 128 * 16; i += 256) sW[i] = W2[i];
    for (int i = t; i < 16 * 128; i += 256) {
        int r = i >> 7, k = i & 127;
        sH[i] = Hm[(size_t)(row0 + r) * 128 + k];
    }
    __syncthreads();
    int r = t >> 4, c = t & 15;
    float acc = 0.f;
#pragma unroll 8
    for (int k = 0; k < 128; k++) acc = fmaf(sH[r * 128 + k], sW[k * 16 + c], acc);
    size_t off = (size_t)(row0 + r) * 16 + c;
    g_h2[off] = acc;
    g_ca[off] = __float2half_rn(acc);
}

// ---------------- 5: SpMM diffusion step, F=16, 16 thr/row (two 8-lane halves) -------
template <bool FINAL>
__global__ void spmm_c16(const __half* __restrict__ in, const float* __restrict__ h,
                         __half* __restrict__ out, float* __restrict__ outf,
                         const float* __restrict__ bias) {
    const int t   = threadIdx.x;
    const int rib = t >> 4;               // row-in-block 0..15
    const int l16 = t & 15;
    const int l8  = l16 & 7;              // half2 lane
    const int eg  = l16 >> 3;             // edge group 0/1
    const int row = blockIdx.x * 16 + rib;
    const size_t base = (size_t)row * CAP;
    const int cnt = g_cnt[row];
    const uint2* __restrict__ ev = g_pack + base;
    const unsigned* __restrict__ inv = (const unsigned*)in;
    float a0 = 0.f, a1 = 0.f;
#pragma unroll 4
    for (int e = eg; e < cnt; e += 2) {
        uint2 p = __ldg(&ev[e]);
        int   c = (int)p.x;
        float v = __uint_as_float(p.y);
        unsigned o = __ldg(&inv[(size_t)c * 8 + l8]);
        float2 f = __half22float2(*(__half2*)&o);
        a0 = fmaf(v, f.x, a0);
        a1 = fmaf(v, f.y, a1);
    }
    a0 += __shfl_xor_sync(0xffffffffu, a0, 8, 16);
    a1 += __shfl_xor_sync(0xffffffffu, a1, 8, 16);
    float2 hh = ((const float2*)h)[(size_t)row * 8 + l8];
    float r0 = C_PROP * a0 + C_RES * hh.x;
    float r1 = C_PROP * a1 + C_RES * hh.y;
    if (FINAL) {
        float2 b = ((const float2*)bias)[l8];
        r0 += b.x;
        r1 += b.y;
        float m = fmaxf(r0, r1);
#pragma unroll
        for (int s = 1; s < 8; s <<= 1)
            m = fmaxf(m, __shfl_xor_sync(0xffffffffu, m, s, 8));
        float ssum = expf(r0 - m) + expf(r1 - m);
#pragma unroll
        for (int s = 1; s < 8; s <<= 1)
            ssum += __shfl_xor_sync(0xffffffffu, ssum, s, 8);
        float lse = m + logf(ssum);
        if (eg == 0)
            ((float2*)outf)[(size_t)row * 8 + l8] = make_float2(r0 - lse, r1 - lse);
    } else {
        if (eg == 0) {
            __half2 hv = __floats2half2_rn(r0, r1);
            ((unsigned*)out)[(size_t)row * 8 + l8] = *(unsigned*)&hv;
        }
    }
}

// ---------------- launch: build || (gemm1,reduce) forked; scale fused in step 1 ------
extern "C" void kernel_launch(void* const* d_in, const int* in_sizes, int n_in,
                              void* d_out, int out_size) {
    const float* x   = (const float*)d_in[0];
    const float* adj = (const float*)d_in[1];
    const float* W1  = (const float*)d_in[2];
    const float* b1  = (const float*)d_in[3];
    const float* W2  = (const float*)d_in[4];
    const float* b2  = (const float*)d_in[5];
    float* out = (float*)d_out;

    void *ph1, *pfa, *pfb, *prl, *ph2, *pca, *pcb;
    cudaGetSymbolAddress(&ph1, g_h1);
    cudaGetSymbolAddress(&pfa, g_fa);
    cudaGetSymbolAddress(&pfb, g_fb);
    cudaGetSymbolAddress(&prl, g_relu);
    cudaGetSymbolAddress(&ph2, g_h2);
    cudaGetSymbolAddress(&pca, g_ca);
    cudaGetSymbolAddress(&pcb, g_cb);
    float*  h1 = (float*)ph1;
    __half* fa = (__half*)pfa;
    __half* fb = (__half*)pfb;
    float*  rl = (float*)prl;
    float*  h2 = (float*)ph2;
    __half* ca = (__half*)pca;
    __half* cb = (__half*)pcb;

    cudaStream_t sB;
    cudaStreamCreateWithFlags(&sB, cudaStreamNonBlocking);
    cudaEvent_t eFork, eJoin;
    cudaEventCreateWithFlags(&eFork, cudaEventDisableTiming);
    cudaEventCreateWithFlags(&eJoin, cudaEventDisableTiming);

    cudaEventRecord(eFork, 0);
    cudaStreamWaitEvent(sB, eFork, 0);

    // branch B: layer-1 dense transform
    gemm1_kernel<<<dim3(N_NODES / 128, HID / 64, KSPLIT), 256, 0, sB>>>(x, W1);
    reduce_kernel<<<N_NODES * HID / 4 / 512, 256, 0, sB>>>();
    cudaEventRecord(eJoin, sB);

    // branch A (main stream): adjacency build
    build_kernel<<<N_NODES / 8, 256>>>(adj);

    cudaStreamWaitEvent(0, eJoin, 0);

    // layer 1: 8 diffusion steps; step 1 fuses scale/pack; step 8 fuses bias+relu
    spmm_h16<true , false><<<N_NODES / 4, 256>>>(fa, h1, fb, nullptr, b1);
    spmm_h16<false, false><<<N_NODES / 4, 256>>>(fb, h1, fa, nullptr, b1);
    spmm_h16<false, false><<<N_NODES / 4, 256>>>(fa, h1, fb, nullptr, b1);
    spmm_h16<false, false><<<N_NODES / 4, 256>>>(fb, h1, fa, nullptr, b1);
    spmm_h16<false, false><<<N_NODES / 4, 256>>>(fa, h1, fb, nullptr, b1);
    spmm_h16<false, false><<<N_NODES / 4, 256>>>(fb, h1, fa, nullptr, b1);
    spmm_h16<false, false><<<N_NODES / 4, 256>>>(fa, h1, fb, nullptr, b1);
    spmm_h16<false, true ><<<N_NODES / 4, 256>>>(fb, h1, nullptr, rl, b1);

    // layer 2: h2 = relu_out @ W2; 8 fp16 diffusion steps; final = bias + log_softmax
    gemm2_kernel<<<N_NODES / 16, 256>>>(rl, W2);
    spmm_c16<false><<<N_NODES / 16, 256>>>(ca, h2, cb, nullptr, b2);
    spmm_c16<false><<<N_NODES / 16, 256>>>(cb, h2, ca, nullptr, b2);
    spmm_c16<false><<<N_NODES / 16, 256>>>(ca, h2, cb, nullptr, b2);
    spmm_c16<false><<<N_NODES / 16, 256>>>(cb, h2, ca, nullptr, b2);
    spmm_c16<false><<<N_NODES / 16, 256>>>(ca, h2, cb, nullptr, b2);
    spmm_c16<false><<<N_NODES / 16, 256>>>(cb, h2, ca, nullptr, b2);
    spmm_c16<false><<<N_NODES / 16, 256>>>(ca, h2, cb, nullptr, b2);
    spmm_c16<true ><<<N_NODES / 16, 256>>>(cb, h2, nullptr, out, b2);

    cudaEventDestroy(eFork);
    cudaEventDestroy(eJoin);
    cudaStreamDestroy(sB);
}